// round 14
// baseline (speedup 1.0000x reference)
#include <cuda_runtime.h>
#include <cuda_bf16.h>
#include <cstdint>

#define BTc 16
#define Nc 1024
#define Dc 128
#define Hc 8
#define HDc 16
#define Mc (BTc*Nc)

// ---- gmem scratch (no allocs allowed) ----
__device__ __nv_bfloat16 g_qh[(size_t)BTc*Hc*Nc*HDc];  // [slab][n][hd]
__device__ __nv_bfloat16 g_ql[(size_t)BTc*Hc*Nc*HDc];
__device__ __nv_bfloat16 g_kh[(size_t)BTc*Hc*Nc*HDc];
__device__ __nv_bfloat16 g_kl[(size_t)BTc*Hc*Nc*HDc];
__device__ __nv_bfloat16 g_vth[(size_t)BTc*Hc*HDc*Nc]; // [slab][hd][n] transposed
__device__ __nv_bfloat16 g_vtl[(size_t)BTc*Hc*HDc*Nc];
__device__ float g_ctx[(size_t)Mc*Dc];

__device__ __forceinline__ float fast_ex2(float x){ float r; asm("ex2.approx.f32 %0,%1;":"=f"(r):"f"(x)); return r; }
__device__ __forceinline__ uint32_t smem_u32(const void* p){ uint32_t a; asm("{ .reg .u64 t; cvta.to.shared.u64 t, %1; cvt.u32.u64 %0, t; }":"=r"(a):"l"(p)); return a; }
__device__ __forceinline__ uint32_t packbf(float x, float y){
    __nv_bfloat162 t = __floats2bfloat162_rn(x, y);   // .x = low half
    return *reinterpret_cast<uint32_t*>(&t);
}
__device__ __forceinline__ void mma16816(float* d, uint32_t a0,uint32_t a1,uint32_t a2,uint32_t a3,
                                         uint32_t b0,uint32_t b1){
    asm volatile("mma.sync.aligned.m16n8k16.row.col.f32.bf16.bf16.f32 "
        "{%0,%1,%2,%3},{%4,%5,%6,%7},{%8,%9},{%0,%1,%2,%3};"
        : "+f"(d[0]),"+f"(d[1]),"+f"(d[2]),"+f"(d[3])
        : "r"(a0),"r"(a1),"r"(a2),"r"(a3),"r"(b0),"r"(b1));
}
#define CP16(dst,src) asm volatile("cp.async.ca.shared.global [%0], [%1], 16;"::"r"(dst),"l"(src):"memory")
#define CP_COMMIT()   asm volatile("cp.async.commit_group;":::"memory")
#define CP_WAIT0()    asm volatile("cp.async.wait_group 0;":::"memory")

// attention smem layout (bytes)
#define O_QH 0
#define O_QL 12288
#define O_KH 24576
#define O_KL 36864
#define O_VH 49152
#define O_VL 57856
#define O_ADJ 66560
#define SMEM_ATTN 201728   // O_ADJ + 2*67584

// projection smem layout (bytes); tiles stride 136 bf16 = 272B/row
#define SPITCH 136
#define P_XH 0
#define P_XL 34816
#define P_WH 69632
#define P_WL 104448
#define P_BIAS 139264
#define SMEM_PROJ 139776

// ============================================================
// Shared mma GEMM tile: C[128,128] = X[128,128] @ W[128,128]^T (bf16x3).
// ============================================================
__device__ __forceinline__ void proj_mma_tile(const float* __restrict__ Xg,
                                              const float* __restrict__ Wg,
                                              const float* __restrict__ bias,
                                              char* smc, int m0, float acc[16][4])
{
    int tid = threadIdx.x;
    __nv_bfloat16* Xh = (__nv_bfloat16*)(smc + P_XH);
    __nv_bfloat16* Xl = (__nv_bfloat16*)(smc + P_XL);
    __nv_bfloat16* Wh = (__nv_bfloat16*)(smc + P_WH);
    __nv_bfloat16* Wl = (__nv_bfloat16*)(smc + P_WL);
    float* bias_s = (float*)(smc + P_BIAS);
    if (tid < 128) bias_s[tid] = bias[tid];

    #pragma unroll
    for (int it = 0; it < 16; ++it) {
        int idx = it*256 + tid; int m = idx >> 5, k4 = (idx & 31)*4;
        float4 v = *(const float4*)(Xg + (size_t)(m0+m)*128 + k4);
        uint32_t H0 = packbf(v.x, v.y), H1 = packbf(v.z, v.w);
        float r0 = v.x - __uint_as_float(H0 << 16);
        float r1 = v.y - __uint_as_float(H0 & 0xffff0000u);
        float r2 = v.z - __uint_as_float(H1 << 16);
        float r3 = v.w - __uint_as_float(H1 & 0xffff0000u);
        *(uint2*)(Xh + m*SPITCH + k4) = make_uint2(H0, H1);
        *(uint2*)(Xl + m*SPITCH + k4) = make_uint2(packbf(r0, r1), packbf(r2, r3));
        float4 w = *(const float4*)(Wg + (size_t)m*128 + k4);
        uint32_t G0 = packbf(w.x, w.y), G1 = packbf(w.z, w.w);
        float s0 = w.x - __uint_as_float(G0 << 16);
        float s1 = w.y - __uint_as_float(G0 & 0xffff0000u);
        float s2 = w.z - __uint_as_float(G1 << 16);
        float s3 = w.w - __uint_as_float(G1 & 0xffff0000u);
        *(uint2*)(Wh + m*SPITCH + k4) = make_uint2(G0, G1);
        *(uint2*)(Wl + m*SPITCH + k4) = make_uint2(packbf(s0, s1), packbf(s2, s3));
    }
    __syncthreads();

    int w = tid >> 5, l = tid & 31;
    int g = l >> 2, c2 = (l & 3)*2;
    int m0w = w*16;
    #pragma unroll
    for (int j = 0; j < 16; ++j) { acc[j][0]=0.f; acc[j][1]=0.f; acc[j][2]=0.f; acc[j][3]=0.f; }

    #pragma unroll
    for (int ks = 0; ks < 8; ++ks) {
        int kb = ks*16;
        uint32_t ah0 = *(const uint32_t*)(Xh + (m0w+g)*SPITCH + kb + c2);
        uint32_t ah1 = *(const uint32_t*)(Xh + (m0w+g+8)*SPITCH + kb + c2);
        uint32_t ah2 = *(const uint32_t*)(Xh + (m0w+g)*SPITCH + kb + c2 + 8);
        uint32_t ah3 = *(const uint32_t*)(Xh + (m0w+g+8)*SPITCH + kb + c2 + 8);
        uint32_t al0 = *(const uint32_t*)(Xl + (m0w+g)*SPITCH + kb + c2);
        uint32_t al1 = *(const uint32_t*)(Xl + (m0w+g+8)*SPITCH + kb + c2);
        uint32_t al2 = *(const uint32_t*)(Xl + (m0w+g)*SPITCH + kb + c2 + 8);
        uint32_t al3 = *(const uint32_t*)(Xl + (m0w+g+8)*SPITCH + kb + c2 + 8);
        #pragma unroll
        for (int j = 0; j < 16; ++j) {
            int n0 = 8*j;
            uint32_t bh0 = *(const uint32_t*)(Wh + (n0+g)*SPITCH + kb + c2);
            uint32_t bh1 = *(const uint32_t*)(Wh + (n0+g)*SPITCH + kb + c2 + 8);
            uint32_t bl0 = *(const uint32_t*)(Wl + (n0+g)*SPITCH + kb + c2);
            uint32_t bl1 = *(const uint32_t*)(Wl + (n0+g)*SPITCH + kb + c2 + 8);
            mma16816(acc[j], ah0,ah1,ah2,ah3, bh0,bh1);
            mma16816(acc[j], ah0,ah1,ah2,ah3, bl0,bl1);
            mma16816(acc[j], al0,al1,al2,al3, bh0,bh1);
        }
    }
    __syncthreads();
}

// ============================================================
// QKV projection (tensorized) + staged coalesced bf16 hi/lo stores
// ============================================================
__global__ void __launch_bounds__(256) proj_qkv_kernel(
    const float* __restrict__ x,
    const float* __restrict__ Wq, const float* __restrict__ bq,
    const float* __restrict__ Wk, const float* __restrict__ bk,
    const float* __restrict__ Wv, const float* __restrict__ bv)
{
    extern __shared__ char smc[];
    int sel = blockIdx.y;
    const float* W    = (sel==0)?Wq:(sel==1)?Wk:Wv;
    const float* bias = (sel==0)?bq:(sel==1)?bk:bv;
    float scale = (sel==0)?(0.25f*1.4426950408889634f):1.0f;
    int m0 = blockIdx.x * 128;

    float acc[16][4];
    proj_mma_tile(x, W, bias, smc, m0, acc);

    float* bias_s = (float*)(smc + P_BIAS);
    __nv_bfloat16* Sh = (__nv_bfloat16*)smc;
    __nv_bfloat16* Sl = Sh + 16384;
    int tid = threadIdx.x, w = tid >> 5, l = tid & 31;
    int g = l >> 2, c2 = (l & 3)*2;
    int r0 = w*16 + g, r1 = r0 + 8;

    #pragma unroll
    for (int j = 0; j < 16; ++j) {
        int n0 = 8*j;
        #pragma unroll
        for (int e = 0; e < 4; ++e) {
            int col = n0 + c2 + (e & 1);
            int r = (e < 2) ? r0 : r1;
            float v = (acc[j][e] + bias_s[col]) * scale;
            __nv_bfloat16 hb = __float2bfloat16_rn(v);
            __nv_bfloat16 lb = __float2bfloat16_rn(v - __bfloat162float(hb));
            int head = col >> 4, hd = col & 15;
            int off = (sel < 2) ? (head*2048 + r*16 + hd)
                                : (head*2048 + hd*128 + r);
            Sh[off] = hb; Sl[off] = lb;
        }
    }
    __syncthreads();

    int bt = m0 / Nc, nbase = m0 % Nc;
    __nv_bfloat16* GH = (sel==0)?g_qh:(sel==1)?g_kh:g_vth;
    __nv_bfloat16* GL = (sel==0)?g_ql:(sel==1)?g_kl:g_vtl;
    const uint4* sh4 = (const uint4*)Sh;
    const uint4* sl4 = (const uint4*)Sl;
    #pragma unroll
    for (int it = 0; it < 8; ++it) {
        int i4 = it*256 + tid;
        int head = i4 >> 8, rem = i4 & 255;
        if (sel < 2) {
            size_t gbase = (((size_t)(bt*Hc + head))*Nc + nbase)*HDc;
            ((uint4*)(GH + gbase))[rem] = sh4[i4];
            ((uint4*)(GL + gbase))[rem] = sl4[i4];
        } else {
            int hd = rem >> 4, n8 = rem & 15;
            size_t gbase = ((size_t)(bt*Hc + head))*HDc*Nc + (size_t)hd*Nc + nbase;
            ((uint4*)(GH + gbase))[n8] = sh4[i4];
            ((uint4*)(GL + gbase))[n8] = sl4[i4];
        }
    }
}

// ============================================================
// O projection (tensorized)
// ============================================================
__global__ void __launch_bounds__(256) proj_o_kernel(
    const float* __restrict__ Wo, const float* __restrict__ bo, float* __restrict__ out)
{
    extern __shared__ char smc[];
    int m0 = blockIdx.x * 128;
    float acc[16][4];
    proj_mma_tile(g_ctx, Wo, bo, smc, m0, acc);

    float* bias_s = (float*)(smc + P_BIAS);
    float* Sf = (float*)smc;   // [128][132]
    int tid = threadIdx.x, w = tid >> 5, l = tid & 31;
    int g = l >> 2, c2 = (l & 3)*2;
    int r0 = w*16 + g, r1 = r0 + 8;
    #pragma unroll
    for (int j = 0; j < 16; ++j) {
        int n0 = 8*j;
        Sf[r0*132 + n0 + c2]     = acc[j][0] + bias_s[n0 + c2];
        Sf[r0*132 + n0 + c2 + 1] = acc[j][1] + bias_s[n0 + c2 + 1];
        Sf[r1*132 + n0 + c2]     = acc[j][2] + bias_s[n0 + c2];
        Sf[r1*132 + n0 + c2 + 1] = acc[j][3] + bias_s[n0 + c2 + 1];
    }
    __syncthreads();
    #pragma unroll
    for (int it = 0; it < 16; ++it) {
        int i4 = it*256 + tid;
        int row = i4 >> 5, c4 = (i4 & 31)*4;
        *(float4*)(out + (size_t)(m0+row)*128 + c4) = *(const float4*)(Sf + row*132 + c4);
    }
}

// ============================================================
// bf16x3 warp-MMA flash attention, 512 threads (16 warps).
// Warp pair (qw, cw): qw = q-tile (16 rows), cw = key-column half (64 cols).
// Pair merges ctx+rowsum via smem at chunk 7 (barrier BEFORE exchange
// writes — adj rows 0-23 double as the exchange buffer and must not be
// clobbered while other warps still read them in their epilogue).
// ============================================================
__device__ __forceinline__ void issue_loads(int it, int t, uint32_t sb,
    const __nv_bfloat16* gqh, const __nv_bfloat16* gql,
    const __nv_bfloat16* gkh, const __nv_bfloat16* gkl,
    const __nv_bfloat16* gvh, const __nv_bfloat16* gvl,
    const float* adjg)
{
    int qt = it >> 3, ch = it & 7, b = it & 1;
    int tt = t & 255, half = t >> 8;            // half 0 -> hi buffers, 1 -> lo
    int row = tt >> 1, hw = tt & 1;
    {
        uint32_t kdst = sb + (half ? O_KL : O_KH) + b*6144 + row*48 + hw*16;
        const __nv_bfloat16* ksrc = (half ? gkl : gkh) + (ch*128+row)*16 + hw*8;
        CP16(kdst, ksrc);
    }
    {
        int vg = tt >> 4, vp = tt & 15;
        uint32_t vdst = sb + (half ? O_VL : O_VH) + b*4352 + vg*272 + vp*16;
        const __nv_bfloat16* vsrc = (half ? gvl : gvh) + vg*1024 + ch*128 + vp*8;
        CP16(vdst, vsrc);
    }
    #pragma unroll
    for (int i = 0; i < 8; ++i) {
        int e = i*512 + t, r2 = e >> 5, q4 = e & 31;   // 128 rows x 32 float4
        CP16(sb + O_ADJ + b*67584 + r2*528 + q4*16,
             adjg + (size_t)(qt*128 + r2)*1024 + ch*128 + q4*4);
    }
    if (ch == 0) {
        int qb = qt & 1;
        uint32_t qdst = sb + (half ? O_QL : O_QH) + qb*6144 + row*48 + hw*16;
        const __nv_bfloat16* qsrc = (half ? gql : gqh) + (qt*128+row)*16 + hw*8;
        CP16(qdst, qsrc);
    }
    CP_COMMIT();
}

__global__ void __launch_bounds__(512,1) attn_mma_kernel(const float* __restrict__ adj)
{
    extern __shared__ char smc[];
    uint32_t sb = smem_u32(smc);
    int t = threadIdx.x, w = t >> 5, l = t & 31;
    int qw = w >> 1, cw = w & 1;
    int g = l >> 2, c2 = (l & 3)*2;
    int bt = blockIdx.x >> 3, h = blockIdx.x & 7, slab = bt*Hc + h;
    int m0 = qw*16;
    int ncol0 = cw*64;                 // my key-column half base

    const __nv_bfloat16* gqh = g_qh + (size_t)slab*Nc*HDc;
    const __nv_bfloat16* gql = g_ql + (size_t)slab*Nc*HDc;
    const __nv_bfloat16* gkh = g_kh + (size_t)slab*Nc*HDc;
    const __nv_bfloat16* gkl = g_kl + (size_t)slab*Nc*HDc;
    const __nv_bfloat16* gvh = g_vth + (size_t)slab*HDc*Nc;
    const __nv_bfloat16* gvl = g_vtl + (size_t)slab*HDc*Nc;
    const float* adjg = adj + ((size_t)bt << 20);

    uint32_t qh0=0,qh1=0,qh2=0,qh3=0, ql0=0,ql1=0,ql2=0,ql3=0;
    float ctx0[4], ctx1[4], sum0 = 0.f, sum1 = 0.f;

    issue_loads(0, t, sb, gqh, gql, gkh, gkl, gvh, gvl, adjg);

    for (int it = 0; it < 64; ++it) {
        CP_WAIT0();
        __syncthreads();
        if (it < 63) issue_loads(it+1, t, sb, gqh, gql, gkh, gkl, gvh, gvl, adjg);

        int qt = it >> 3, ch = it & 7, b = it & 1;
        const __nv_bfloat16* sKh = (const __nv_bfloat16*)(smc + O_KH + b*6144);
        const __nv_bfloat16* sKl = (const __nv_bfloat16*)(smc + O_KL + b*6144);
        const __nv_bfloat16* sVh = (const __nv_bfloat16*)(smc + O_VH + b*4352);
        const __nv_bfloat16* sVl = (const __nv_bfloat16*)(smc + O_VL + b*4352);
        const float* sAdj = (const float*)(smc + O_ADJ + b*67584);

        if (ch == 0) {
            const __nv_bfloat16* sQh = (const __nv_bfloat16*)(smc + O_QH + (qt&1)*6144);
            const __nv_bfloat16* sQl = (const __nv_bfloat16*)(smc + O_QL + (qt&1)*6144);
            qh0 = *(const uint32_t*)(sQh + (m0+g)*24 + c2);
            qh1 = *(const uint32_t*)(sQh + (m0+g+8)*24 + c2);
            qh2 = *(const uint32_t*)(sQh + (m0+g)*24 + c2 + 8);
            qh3 = *(const uint32_t*)(sQh + (m0+g+8)*24 + c2 + 8);
            ql0 = *(const uint32_t*)(sQl + (m0+g)*24 + c2);
            ql1 = *(const uint32_t*)(sQl + (m0+g+8)*24 + c2);
            ql2 = *(const uint32_t*)(sQl + (m0+g)*24 + c2 + 8);
            ql3 = *(const uint32_t*)(sQl + (m0+g+8)*24 + c2 + 8);
            ctx0[0]=ctx0[1]=ctx0[2]=ctx0[3]=0.f;
            ctx1[0]=ctx1[1]=ctx1[2]=ctx1[3]=0.f;
            sum0 = 0.f; sum1 = 0.f;
        }

        // ---- S = Q K^T over my 64 cols (bf16x3) ----
        float sacc[8][4];
        #pragma unroll
        for (int j = 0; j < 8; ++j) { sacc[j][0]=0.f; sacc[j][1]=0.f; sacc[j][2]=0.f; sacc[j][3]=0.f; }
        #pragma unroll
        for (int j = 0; j < 8; ++j) {
            int n0 = ncol0 + 8*j;
            uint32_t bh0 = *(const uint32_t*)(sKh + (n0+g)*24 + c2);
            uint32_t bh1 = *(const uint32_t*)(sKh + (n0+g)*24 + c2 + 8);
            uint32_t bl0 = *(const uint32_t*)(sKl + (n0+g)*24 + c2);
            uint32_t bl1 = *(const uint32_t*)(sKl + (n0+g)*24 + c2 + 8);
            mma16816(sacc[j], qh0,qh1,qh2,qh3, bh0,bh1);
            mma16816(sacc[j], qh0,qh1,qh2,qh3, bl0,bl1);
            mma16816(sacc[j], ql0,ql1,ql2,ql3, bh0,bh1);
        }

        // ---- epilogue: p = ex2(s)*adj, bf16 hi/lo A-frags ----
        uint32_t phA[8], phB[8], plA[8], plB[8];
        #pragma unroll
        for (int j = 0; j < 8; ++j) {
            int n0 = ncol0 + 8*j;
            float2 aA = *(const float2*)(sAdj + (m0+g)*132 + n0 + c2);
            float2 aB = *(const float2*)(sAdj + (m0+g+8)*132 + n0 + c2);
            float p0 = fast_ex2(sacc[j][0]) * aA.x;
            float p1 = fast_ex2(sacc[j][1]) * aA.y;
            float p2 = fast_ex2(sacc[j][2]) * aB.x;
            float p3 = fast_ex2(sacc[j][3]) * aB.y;
            sum0 += p0 + p1; sum1 += p2 + p3;
            uint32_t hA = packbf(p0, p1), hB = packbf(p2, p3);
            phA[j] = hA; phB[j] = hB;
            plA[j] = packbf(p0 - __uint_as_float(hA << 16), p1 - __uint_as_float(hA & 0xffff0000u));
            plB[j] = packbf(p2 - __uint_as_float(hB << 16), p3 - __uint_as_float(hB & 0xffff0000u));
        }

        // ---- ctx += P V over my 64-col k-half (bf16x3) ----
        #pragma unroll
        for (int kk = 0; kk < 4; ++kk) {
            int k0 = ncol0 + 16*kk;
            uint32_t vh0 = *(const uint32_t*)(sVh + g*136 + k0 + c2);
            uint32_t vh1 = *(const uint32_t*)(sVh + g*136 + k0 + c2 + 8);
            uint32_t vl0 = *(const uint32_t*)(sVl + g*136 + k0 + c2);
            uint32_t vl1 = *(const uint32_t*)(sVl + g*136 + k0 + c2 + 8);
            uint32_t wh0 = *(const uint32_t*)(sVh + (g+8)*136 + k0 + c2);
            uint32_t wh1 = *(const uint32_t*)(sVh + (g+8)*136 + k0 + c2 + 8);
            uint32_t wl0 = *(const uint32_t*)(sVl + (g+8)*136 + k0 + c2);
            uint32_t wl1 = *(const uint32_t*)(sVl + (g+8)*136 + k0 + c2 + 8);
            uint32_t a0 = phA[2*kk], a1 = phB[2*kk], a2 = phA[2*kk+1], a3 = phB[2*kk+1];
            uint32_t e0 = plA[2*kk], e1 = plB[2*kk], e2 = plA[2*kk+1], e3 = plB[2*kk+1];
            mma16816(ctx0, a0,a1,a2,a3, vh0,vh1);
            mma16816(ctx0, a0,a1,a2,a3, vl0,vl1);
            mma16816(ctx0, e0,e1,e2,e3, vh0,vh1);
            mma16816(ctx1, a0,a1,a2,a3, wh0,wh1);
            mma16816(ctx1, a0,a1,a2,a3, wl0,wl1);
            mma16816(ctx1, e0,e1,e2,e3, wh0,wh1);
        }

        if (ch == 7) {
            // quad-reduce rowsums (within my col half)
            float s0 = sum0, s1 = sum1;
            s0 += __shfl_xor_sync(0xffffffffu, s0, 1);
            s0 += __shfl_xor_sync(0xffffffffu, s0, 2);
            s1 += __shfl_xor_sync(0xffffffffu, s1, 1);
            s1 += __shfl_xor_sync(0xffffffffu, s1, 2);
            // BARRIER before exchange writes: the exchange reuses adj
            // buffer b (rows 0-23) — all warps must finish their epilogue
            // adj reads first.  ch==7 is block-uniform so this is legal.
            __syncthreads();
            float* ex = (float*)(smc + O_ADJ + b*67584);
            int slot = (qw*32 + l)*12;
            if (cw == 1) {
                ex[slot+0] = ctx0[0]; ex[slot+1] = ctx0[1];
                ex[slot+2] = ctx0[2]; ex[slot+3] = ctx0[3];
                ex[slot+4] = ctx1[0]; ex[slot+5] = ctx1[1];
                ex[slot+6] = ctx1[2]; ex[slot+7] = ctx1[3];
                ex[slot+8] = s0; ex[slot+9] = s1;
            }
            __syncthreads();
            if (cw == 0) {
                float c00 = ctx0[0] + ex[slot+0], c01 = ctx0[1] + ex[slot+1];
                float c02 = ctx0[2] + ex[slot+2], c03 = ctx0[3] + ex[slot+3];
                float c10 = ctx1[0] + ex[slot+4], c11 = ctx1[1] + ex[slot+5];
                float c12 = ctx1[2] + ex[slot+6], c13 = ctx1[3] + ex[slot+7];
                float t0 = s0 + ex[slot+8], t1 = s1 + ex[slot+9];
                float inv0 = 1.0f / (t0 + 1e-8f), inv1 = 1.0f / (t1 + 1e-8f);
                int qr = qt*128 + m0 + g;
                float* op  = g_ctx + ((size_t)(bt*Nc + qr))*Dc + h*HDc;
                float* op2 = op + 8*Dc;
                *(float2*)(op + c2)      = make_float2(c00*inv0, c01*inv0);
                *(float2*)(op + 8 + c2)  = make_float2(c10*inv0, c11*inv0);
                *(float2*)(op2 + c2)     = make_float2(c02*inv1, c03*inv1);
                *(float2*)(op2 + 8 + c2) = make_float2(c12*inv1, c13*inv1);
            }
        }
    }
}

// ============================================================
extern "C" void kernel_launch(void* const* d_in, const int* in_sizes, int n_in,
                              void* d_out, int out_size)
{
    const float* x   = (const float*)d_in[0];
    const float* adj = (const float*)d_in[1];
    const float* Wq  = (const float*)d_in[2];
    const float* bq  = (const float*)d_in[3];
    const float* Wk  = (const float*)d_in[4];
    const float* bk  = (const float*)d_in[5];
    const float* Wv  = (const float*)d_in[6];
    const float* bv  = (const float*)d_in[7];
    const float* Wo  = (const float*)d_in[8];
    const float* bo  = (const float*)d_in[9];
    float* out = (float*)d_out;

    cudaFuncSetAttribute(proj_qkv_kernel, cudaFuncAttributeMaxDynamicSharedMemorySize, SMEM_PROJ);
    cudaFuncSetAttribute(proj_o_kernel,   cudaFuncAttributeMaxDynamicSharedMemorySize, SMEM_PROJ);
    cudaFuncSetAttribute(attn_mma_kernel, cudaFuncAttributeMaxDynamicSharedMemorySize, SMEM_ATTN);

    dim3 gqkv(Mc/128, 3);
    proj_qkv_kernel<<<gqkv, 256, SMEM_PROJ>>>(x, Wq, bq, Wk, bk, Wv, bv);
    attn_mma_kernel<<<BTc*Hc, 512, SMEM_ATTN>>>(adj);
    proj_o_kernel<<<Mc/128, 256, SMEM_PROJ>>>(Wo, bo, out);
}

// round 15
// speedup vs baseline: 1.1153x; 1.1153x over previous
#include <cuda_runtime.h>
#include <cuda_bf16.h>
#include <cuda_fp16.h>
#include <cstdint>

#define BTc 16
#define Nc 1024
#define Dc 128
#define Hc 8
#define HDc 16
#define Mc (BTc*Nc)

// ---- gmem scratch (no allocs allowed) ----
__device__ __nv_bfloat16 g_qh[(size_t)BTc*Hc*Nc*HDc];  // [slab][n][hd]
__device__ __nv_bfloat16 g_ql[(size_t)BTc*Hc*Nc*HDc];
__device__ __nv_bfloat16 g_kh[(size_t)BTc*Hc*Nc*HDc];
__device__ __nv_bfloat16 g_kl[(size_t)BTc*Hc*Nc*HDc];
__device__ __nv_bfloat16 g_vth[(size_t)BTc*Hc*HDc*Nc]; // [slab][hd][n] transposed
__device__ __nv_bfloat16 g_vtl[(size_t)BTc*Hc*HDc*Nc];
__device__ __half g_adjh[(size_t)BTc*Nc*Nc];           // fp16 copy of adj (32MB)
__device__ float g_ctx[(size_t)Mc*Dc];

__device__ __forceinline__ float fast_ex2(float x){ float r; asm("ex2.approx.f32 %0,%1;":"=f"(r):"f"(x)); return r; }
__device__ __forceinline__ uint32_t smem_u32(const void* p){ uint32_t a; asm("{ .reg .u64 t; cvta.to.shared.u64 t, %1; cvt.u32.u64 %0, t; }":"=r"(a):"l"(p)); return a; }
__device__ __forceinline__ uint32_t packbf(float x, float y){
    __nv_bfloat162 t = __floats2bfloat162_rn(x, y);   // .x = low half
    return *reinterpret_cast<uint32_t*>(&t);
}
__device__ __forceinline__ void mma16816(float* d, uint32_t a0,uint32_t a1,uint32_t a2,uint32_t a3,
                                         uint32_t b0,uint32_t b1){
    asm volatile("mma.sync.aligned.m16n8k16.row.col.f32.bf16.bf16.f32 "
        "{%0,%1,%2,%3},{%4,%5,%6,%7},{%8,%9},{%0,%1,%2,%3};"
        : "+f"(d[0]),"+f"(d[1]),"+f"(d[2]),"+f"(d[3])
        : "r"(a0),"r"(a1),"r"(a2),"r"(a3),"r"(b0),"r"(b1));
}
#define CP16(dst,src) asm volatile("cp.async.ca.shared.global [%0], [%1], 16;"::"r"(dst),"l"(src):"memory")
#define CP_COMMIT()   asm volatile("cp.async.commit_group;":::"memory")
#define CP_WAIT0()    asm volatile("cp.async.wait_group 0;":::"memory")

// attention smem layout (bytes)
// Q/K rows: 24 bf16 (48B). Vt rows: 136 bf16 (272B). adj rows: 136 half (272B).
#define O_QH 0
#define O_QL 12288
#define O_KH 24576
#define O_KL 36864
#define O_VH 49152
#define O_VL 57856
#define O_ADJ 66560
#define ADJ_BUF 34816          // 128 rows x 272B pitch
#define SMEM_ATTN (O_ADJ + 2*ADJ_BUF)   // 136192

// projection smem layout (bytes); tiles stride 136 bf16 = 272B/row
#define SPITCH 136
#define P_XH 0
#define P_XL 34816
#define P_WH 69632
#define P_WL 104448
#define P_BIAS 139264
#define SMEM_PROJ 139776

// ============================================================
// Shared mma GEMM tile: C[128,128] = X[128,128] @ W[128,128]^T (bf16x3).
// ============================================================
__device__ __forceinline__ void proj_mma_tile(const float* __restrict__ Xg,
                                              const float* __restrict__ Wg,
                                              const float* __restrict__ bias,
                                              char* smc, int m0, float acc[16][4])
{
    int tid = threadIdx.x;
    __nv_bfloat16* Xh = (__nv_bfloat16*)(smc + P_XH);
    __nv_bfloat16* Xl = (__nv_bfloat16*)(smc + P_XL);
    __nv_bfloat16* Wh = (__nv_bfloat16*)(smc + P_WH);
    __nv_bfloat16* Wl = (__nv_bfloat16*)(smc + P_WL);
    float* bias_s = (float*)(smc + P_BIAS);
    if (tid < 128) bias_s[tid] = bias[tid];

    #pragma unroll
    for (int it = 0; it < 16; ++it) {
        int idx = it*256 + tid; int m = idx >> 5, k4 = (idx & 31)*4;
        float4 v = *(const float4*)(Xg + (size_t)(m0+m)*128 + k4);
        uint32_t H0 = packbf(v.x, v.y), H1 = packbf(v.z, v.w);
        float r0 = v.x - __uint_as_float(H0 << 16);
        float r1 = v.y - __uint_as_float(H0 & 0xffff0000u);
        float r2 = v.z - __uint_as_float(H1 << 16);
        float r3 = v.w - __uint_as_float(H1 & 0xffff0000u);
        *(uint2*)(Xh + m*SPITCH + k4) = make_uint2(H0, H1);
        *(uint2*)(Xl + m*SPITCH + k4) = make_uint2(packbf(r0, r1), packbf(r2, r3));
        float4 w = *(const float4*)(Wg + (size_t)m*128 + k4);
        uint32_t G0 = packbf(w.x, w.y), G1 = packbf(w.z, w.w);
        float s0 = w.x - __uint_as_float(G0 << 16);
        float s1 = w.y - __uint_as_float(G0 & 0xffff0000u);
        float s2 = w.z - __uint_as_float(G1 << 16);
        float s3 = w.w - __uint_as_float(G1 & 0xffff0000u);
        *(uint2*)(Wh + m*SPITCH + k4) = make_uint2(G0, G1);
        *(uint2*)(Wl + m*SPITCH + k4) = make_uint2(packbf(s0, s1), packbf(s2, s3));
    }
    __syncthreads();

    int w = tid >> 5, l = tid & 31;
    int g = l >> 2, c2 = (l & 3)*2;
    int m0w = w*16;
    #pragma unroll
    for (int j = 0; j < 16; ++j) { acc[j][0]=0.f; acc[j][1]=0.f; acc[j][2]=0.f; acc[j][3]=0.f; }

    #pragma unroll
    for (int ks = 0; ks < 8; ++ks) {
        int kb = ks*16;
        uint32_t ah0 = *(const uint32_t*)(Xh + (m0w+g)*SPITCH + kb + c2);
        uint32_t ah1 = *(const uint32_t*)(Xh + (m0w+g+8)*SPITCH + kb + c2);
        uint32_t ah2 = *(const uint32_t*)(Xh + (m0w+g)*SPITCH + kb + c2 + 8);
        uint32_t ah3 = *(const uint32_t*)(Xh + (m0w+g+8)*SPITCH + kb + c2 + 8);
        uint32_t al0 = *(const uint32_t*)(Xl + (m0w+g)*SPITCH + kb + c2);
        uint32_t al1 = *(const uint32_t*)(Xl + (m0w+g+8)*SPITCH + kb + c2);
        uint32_t al2 = *(const uint32_t*)(Xl + (m0w+g)*SPITCH + kb + c2 + 8);
        uint32_t al3 = *(const uint32_t*)(Xl + (m0w+g+8)*SPITCH + kb + c2 + 8);
        #pragma unroll
        for (int j = 0; j < 16; ++j) {
            int n0 = 8*j;
            uint32_t bh0 = *(const uint32_t*)(Wh + (n0+g)*SPITCH + kb + c2);
            uint32_t bh1 = *(const uint32_t*)(Wh + (n0+g)*SPITCH + kb + c2 + 8);
            uint32_t bl0 = *(const uint32_t*)(Wl + (n0+g)*SPITCH + kb + c2);
            uint32_t bl1 = *(const uint32_t*)(Wl + (n0+g)*SPITCH + kb + c2 + 8);
            mma16816(acc[j], ah0,ah1,ah2,ah3, bh0,bh1);
            mma16816(acc[j], ah0,ah1,ah2,ah3, bl0,bl1);
            mma16816(acc[j], al0,al1,al2,al3, bh0,bh1);
        }
    }
    __syncthreads();
}

// ============================================================
// QKV projection (tensorized) + staged coalesced bf16 hi/lo stores.
// grid.y == 3: adj f32 -> fp16 conversion slice (memory-only CTAs).
// ============================================================
__global__ void __launch_bounds__(256) proj_qkv_kernel(
    const float* __restrict__ x, const float* __restrict__ adj,
    const float* __restrict__ Wq, const float* __restrict__ bq,
    const float* __restrict__ Wk, const float* __restrict__ bk,
    const float* __restrict__ Wv, const float* __restrict__ bv)
{
    extern __shared__ char smc[];
    int sel = blockIdx.y;

    if (sel == 3) {
        // convert adj (16M f32) to fp16; 128 CTAs x 256 thr x 128 float4
        const float4* src = (const float4*)adj;
        uint2* dst = (uint2*)g_adjh;
        size_t base = (size_t)blockIdx.x * 32768;
        #pragma unroll 4
        for (int i = 0; i < 128; ++i) {
            size_t idx = base + (size_t)i*256 + threadIdx.x;
            float4 v = src[idx];
            __half2 a = __floats2half2_rn(v.x, v.y);
            __half2 b = __floats2half2_rn(v.z, v.w);
            dst[idx] = make_uint2(*(uint32_t*)&a, *(uint32_t*)&b);
        }
        return;
    }

    const float* W    = (sel==0)?Wq:(sel==1)?Wk:Wv;
    const float* bias = (sel==0)?bq:(sel==1)?bk:bv;
    float scale = (sel==0)?(0.25f*1.4426950408889634f):1.0f;
    int m0 = blockIdx.x * 128;

    float acc[16][4];
    proj_mma_tile(x, W, bias, smc, m0, acc);

    float* bias_s = (float*)(smc + P_BIAS);
    __nv_bfloat16* Sh = (__nv_bfloat16*)smc;
    __nv_bfloat16* Sl = Sh + 16384;
    int tid = threadIdx.x, w = tid >> 5, l = tid & 31;
    int g = l >> 2, c2 = (l & 3)*2;
    int r0 = w*16 + g, r1 = r0 + 8;

    #pragma unroll
    for (int j = 0; j < 16; ++j) {
        int n0 = 8*j;
        #pragma unroll
        for (int e = 0; e < 4; ++e) {
            int col = n0 + c2 + (e & 1);
            int r = (e < 2) ? r0 : r1;
            float v = (acc[j][e] + bias_s[col]) * scale;
            __nv_bfloat16 hb = __float2bfloat16_rn(v);
            __nv_bfloat16 lb = __float2bfloat16_rn(v - __bfloat162float(hb));
            int head = col >> 4, hd = col & 15;
            int off = (sel < 2) ? (head*2048 + r*16 + hd)
                                : (head*2048 + hd*128 + r);
            Sh[off] = hb; Sl[off] = lb;
        }
    }
    __syncthreads();

    int bt = m0 / Nc, nbase = m0 % Nc;
    __nv_bfloat16* GH = (sel==0)?g_qh:(sel==1)?g_kh:g_vth;
    __nv_bfloat16* GL = (sel==0)?g_ql:(sel==1)?g_kl:g_vtl;
    const uint4* sh4 = (const uint4*)Sh;
    const uint4* sl4 = (const uint4*)Sl;
    #pragma unroll
    for (int it = 0; it < 8; ++it) {
        int i4 = it*256 + tid;
        int head = i4 >> 8, rem = i4 & 255;
        if (sel < 2) {
            size_t gbase = (((size_t)(bt*Hc + head))*Nc + nbase)*HDc;
            ((uint4*)(GH + gbase))[rem] = sh4[i4];
            ((uint4*)(GL + gbase))[rem] = sl4[i4];
        } else {
            int hd = rem >> 4, n8 = rem & 15;
            size_t gbase = ((size_t)(bt*Hc + head))*HDc*Nc + (size_t)hd*Nc + nbase;
            ((uint4*)(GH + gbase))[n8] = sh4[i4];
            ((uint4*)(GL + gbase))[n8] = sl4[i4];
        }
    }
}

// ============================================================
// O projection (tensorized)
// ============================================================
__global__ void __launch_bounds__(256) proj_o_kernel(
    const float* __restrict__ Wo, const float* __restrict__ bo, float* __restrict__ out)
{
    extern __shared__ char smc[];
    int m0 = blockIdx.x * 128;
    float acc[16][4];
    proj_mma_tile(g_ctx, Wo, bo, smc, m0, acc);

    float* bias_s = (float*)(smc + P_BIAS);
    float* Sf = (float*)smc;   // [128][132]
    int tid = threadIdx.x, w = tid >> 5, l = tid & 31;
    int g = l >> 2, c2 = (l & 3)*2;
    int r0 = w*16 + g, r1 = r0 + 8;
    #pragma unroll
    for (int j = 0; j < 16; ++j) {
        int n0 = 8*j;
        Sf[r0*132 + n0 + c2]     = acc[j][0] + bias_s[n0 + c2];
        Sf[r0*132 + n0 + c2 + 1] = acc[j][1] + bias_s[n0 + c2 + 1];
        Sf[r1*132 + n0 + c2]     = acc[j][2] + bias_s[n0 + c2];
        Sf[r1*132 + n0 + c2 + 1] = acc[j][3] + bias_s[n0 + c2 + 1];
    }
    __syncthreads();
    #pragma unroll
    for (int it = 0; it < 16; ++it) {
        int i4 = it*256 + tid;
        int row = i4 >> 5, c4 = (i4 & 31)*4;
        *(float4*)(out + (size_t)(m0+row)*128 + c4) = *(const float4*)(Sf + row*132 + c4);
    }
}

// ============================================================
// bf16x3 warp-MMA flash attention (R12 proven shape: 256 thr, 8 warps,
// warp = 16 q-rows x 128 cols).  adj now fp16 from g_adjh: halves the
// dominant cp.async stream and the adj LDS wavefronts.
// ============================================================
__device__ __forceinline__ void issue_loads(int it, int t, uint32_t sb,
    const __nv_bfloat16* gqh, const __nv_bfloat16* gql,
    const __nv_bfloat16* gkh, const __nv_bfloat16* gkl,
    const __nv_bfloat16* gvh, const __nv_bfloat16* gvl,
    const __half* adjh)
{
    int qt = it >> 3, ch = it & 7, b = it & 1;
    int row = t >> 1, hw = t & 1;
    CP16(sb + O_KH + b*6144 + row*48 + hw*16, gkh + (ch*128+row)*16 + hw*8);
    CP16(sb + O_KL + b*6144 + row*48 + hw*16, gkl + (ch*128+row)*16 + hw*8);
    int vg = t >> 4, vp = t & 15;
    CP16(sb + O_VH + b*4352 + vg*272 + vp*16, gvh + vg*1024 + ch*128 + vp*8);
    CP16(sb + O_VL + b*4352 + vg*272 + vp*16, gvl + vg*1024 + ch*128 + vp*8);
    #pragma unroll
    for (int i = 0; i < 8; ++i) {
        int e = i*256 + t, r2 = e >> 4, q8 = e & 15;   // 128 rows x 16 x 16B (fp16)
        CP16(sb + O_ADJ + b*ADJ_BUF + r2*272 + q8*16,
             adjh + (size_t)(qt*128 + r2)*1024 + ch*128 + q8*8);
    }
    if (ch == 0) {
        int qb = qt & 1;
        CP16(sb + O_QH + qb*6144 + row*48 + hw*16, gqh + (qt*128+row)*16 + hw*8);
        CP16(sb + O_QL + qb*6144 + row*48 + hw*16, gql + (qt*128+row)*16 + hw*8);
    }
    CP_COMMIT();
}

__global__ void __launch_bounds__(256,1) attn_mma_kernel()
{
    extern __shared__ char smc[];
    uint32_t sb = smem_u32(smc);
    int t = threadIdx.x, w = t >> 5, l = t & 31;
    int g = l >> 2, c2 = (l & 3)*2;
    int bt = blockIdx.x >> 3, h = blockIdx.x & 7, slab = bt*Hc + h;
    int m0 = w*16;

    const __nv_bfloat16* gqh = g_qh + (size_t)slab*Nc*HDc;
    const __nv_bfloat16* gql = g_ql + (size_t)slab*Nc*HDc;
    const __nv_bfloat16* gkh = g_kh + (size_t)slab*Nc*HDc;
    const __nv_bfloat16* gkl = g_kl + (size_t)slab*Nc*HDc;
    const __nv_bfloat16* gvh = g_vth + (size_t)slab*HDc*Nc;
    const __nv_bfloat16* gvl = g_vtl + (size_t)slab*HDc*Nc;
    const __half* adjh = g_adjh + ((size_t)bt << 20);

    uint32_t qh0=0,qh1=0,qh2=0,qh3=0, ql0=0,ql1=0,ql2=0,ql3=0;
    float ctx0[4], ctx1[4], sum0 = 0.f, sum1 = 0.f;

    issue_loads(0, t, sb, gqh, gql, gkh, gkl, gvh, gvl, adjh);

    for (int it = 0; it < 64; ++it) {
        CP_WAIT0();
        __syncthreads();
        if (it < 63) issue_loads(it+1, t, sb, gqh, gql, gkh, gkl, gvh, gvl, adjh);

        int qt = it >> 3, ch = it & 7, b = it & 1;
        const __nv_bfloat16* sKh = (const __nv_bfloat16*)(smc + O_KH + b*6144);
        const __nv_bfloat16* sKl = (const __nv_bfloat16*)(smc + O_KL + b*6144);
        const __nv_bfloat16* sVh = (const __nv_bfloat16*)(smc + O_VH + b*4352);
        const __nv_bfloat16* sVl = (const __nv_bfloat16*)(smc + O_VL + b*4352);
        const __half* sAdj = (const __half*)(smc + O_ADJ + b*ADJ_BUF);

        if (ch == 0) {
            const __nv_bfloat16* sQh = (const __nv_bfloat16*)(smc + O_QH + (qt&1)*6144);
            const __nv_bfloat16* sQl = (const __nv_bfloat16*)(smc + O_QL + (qt&1)*6144);
            qh0 = *(const uint32_t*)(sQh + (m0+g)*24 + c2);
            qh1 = *(const uint32_t*)(sQh + (m0+g+8)*24 + c2);
            qh2 = *(const uint32_t*)(sQh + (m0+g)*24 + c2 + 8);
            qh3 = *(const uint32_t*)(sQh + (m0+g+8)*24 + c2 + 8);
            ql0 = *(const uint32_t*)(sQl + (m0+g)*24 + c2);
            ql1 = *(const uint32_t*)(sQl + (m0+g+8)*24 + c2);
            ql2 = *(const uint32_t*)(sQl + (m0+g)*24 + c2 + 8);
            ql3 = *(const uint32_t*)(sQl + (m0+g+8)*24 + c2 + 8);
            ctx0[0]=ctx0[1]=ctx0[2]=ctx0[3]=0.f;
            ctx1[0]=ctx1[1]=ctx1[2]=ctx1[3]=0.f;
            sum0 = 0.f; sum1 = 0.f;
        }

        // ---- S = Q K^T (bf16x3) ----
        float sacc[16][4];
        #pragma unroll
        for (int j = 0; j < 16; ++j) { sacc[j][0]=0.f; sacc[j][1]=0.f; sacc[j][2]=0.f; sacc[j][3]=0.f; }
        #pragma unroll
        for (int j = 0; j < 16; ++j) {
            int n0 = 8*j;
            uint32_t bh0 = *(const uint32_t*)(sKh + (n0+g)*24 + c2);
            uint32_t bh1 = *(const uint32_t*)(sKh + (n0+g)*24 + c2 + 8);
            uint32_t bl0 = *(const uint32_t*)(sKl + (n0+g)*24 + c2);
            uint32_t bl1 = *(const uint32_t*)(sKl + (n0+g)*24 + c2 + 8);
            mma16816(sacc[j], qh0,qh1,qh2,qh3, bh0,bh1);
            mma16816(sacc[j], qh0,qh1,qh2,qh3, bl0,bl1);
            mma16816(sacc[j], ql0,ql1,ql2,ql3, bh0,bh1);
        }

        // ---- epilogue: p = ex2(s)*adj (adj fp16), bf16 hi/lo A-frags ----
        uint32_t phA[16], phB[16], plA[16], plB[16];
        #pragma unroll
        for (int j = 0; j < 16; ++j) {
            __half2 hA2 = *(const __half2*)(sAdj + (m0+g)*136 + 8*j + c2);
            __half2 hB2 = *(const __half2*)(sAdj + (m0+g+8)*136 + 8*j + c2);
            float2 aA = __half22float2(hA2);
            float2 aB = __half22float2(hB2);
            float p0 = fast_ex2(sacc[j][0]) * aA.x;
            float p1 = fast_ex2(sacc[j][1]) * aA.y;
            float p2 = fast_ex2(sacc[j][2]) * aB.x;
            float p3 = fast_ex2(sacc[j][3]) * aB.y;
            sum0 += p0 + p1; sum1 += p2 + p3;
            uint32_t hA = packbf(p0, p1), hB = packbf(p2, p3);
            phA[j] = hA; phB[j] = hB;
            plA[j] = packbf(p0 - __uint_as_float(hA << 16), p1 - __uint_as_float(hA & 0xffff0000u));
            plB[j] = packbf(p2 - __uint_as_float(hB << 16), p3 - __uint_as_float(hB & 0xffff0000u));
        }

        // ---- ctx += P V (bf16x3) ----
        #pragma unroll
        for (int kk = 0; kk < 8; ++kk) {
            int k0 = 16*kk;
            uint32_t vh0 = *(const uint32_t*)(sVh + g*136 + k0 + c2);
            uint32_t vh1 = *(const uint32_t*)(sVh + g*136 + k0 + c2 + 8);
            uint32_t vl0 = *(const uint32_t*)(sVl + g*136 + k0 + c2);
            uint32_t vl1 = *(const uint32_t*)(sVl + g*136 + k0 + c2 + 8);
            uint32_t wh0 = *(const uint32_t*)(sVh + (g+8)*136 + k0 + c2);
            uint32_t wh1 = *(const uint32_t*)(sVh + (g+8)*136 + k0 + c2 + 8);
            uint32_t wl0 = *(const uint32_t*)(sVl + (g+8)*136 + k0 + c2);
            uint32_t wl1 = *(const uint32_t*)(sVl + (g+8)*136 + k0 + c2 + 8);
            uint32_t a0 = phA[2*kk], a1 = phB[2*kk], a2 = phA[2*kk+1], a3 = phB[2*kk+1];
            uint32_t e0 = plA[2*kk], e1 = plB[2*kk], e2 = plA[2*kk+1], e3 = plB[2*kk+1];
            mma16816(ctx0, a0,a1,a2,a3, vh0,vh1);
            mma16816(ctx0, a0,a1,a2,a3, vl0,vl1);
            mma16816(ctx0, e0,e1,e2,e3, vh0,vh1);
            mma16816(ctx1, a0,a1,a2,a3, wh0,wh1);
            mma16816(ctx1, a0,a1,a2,a3, wl0,wl1);
            mma16816(ctx1, e0,e1,e2,e3, wh0,wh1);
        }

        if (ch == 7) {
            float s0 = sum0, s1 = sum1;
            s0 += __shfl_xor_sync(0xffffffffu, s0, 1);
            s0 += __shfl_xor_sync(0xffffffffu, s0, 2);
            s1 += __shfl_xor_sync(0xffffffffu, s1, 1);
            s1 += __shfl_xor_sync(0xffffffffu, s1, 2);
            float inv0 = 1.0f / (s0 + 1e-8f), inv1 = 1.0f / (s1 + 1e-8f);
            int qr = qt*128 + m0 + g;
            float* op  = g_ctx + ((size_t)(bt*Nc + qr))*Dc + h*HDc;
            float* op2 = op + 8*Dc;
            float2 o;
            o.x = ctx0[0]*inv0; o.y = ctx0[1]*inv0; *(float2*)(op + c2) = o;
            o.x = ctx1[0]*inv0; o.y = ctx1[1]*inv0; *(float2*)(op + 8 + c2) = o;
            o.x = ctx0[2]*inv1; o.y = ctx0[3]*inv1; *(float2*)(op2 + c2) = o;
            o.x = ctx1[2]*inv1; o.y = ctx1[3]*inv1; *(float2*)(op2 + 8 + c2) = o;
        }
    }
}

// ============================================================
extern "C" void kernel_launch(void* const* d_in, const int* in_sizes, int n_in,
                              void* d_out, int out_size)
{
    const float* x   = (const float*)d_in[0];
    const float* adj = (const float*)d_in[1];
    const float* Wq  = (const float*)d_in[2];
    const float* bq  = (const float*)d_in[3];
    const float* Wk  = (const float*)d_in[4];
    const float* bk  = (const float*)d_in[5];
    const float* Wv  = (const float*)d_in[6];
    const float* bv  = (const float*)d_in[7];
    const float* Wo  = (const float*)d_in[8];
    const float* bo  = (const float*)d_in[9];
    float* out = (float*)d_out;

    cudaFuncSetAttribute(proj_qkv_kernel, cudaFuncAttributeMaxDynamicSharedMemorySize, SMEM_PROJ);
    cudaFuncSetAttribute(proj_o_kernel,   cudaFuncAttributeMaxDynamicSharedMemorySize, SMEM_PROJ);
    cudaFuncSetAttribute(attn_mma_kernel, cudaFuncAttributeMaxDynamicSharedMemorySize, SMEM_ATTN);

    dim3 gqkv(Mc/128, 4);   // y=0..2: Q/K/V GEMM; y=3: adj f32->fp16 conversion
    proj_qkv_kernel<<<gqkv, 256, SMEM_PROJ>>>(x, adj, Wq, bq, Wk, bk, Wv, bv);
    attn_mma_kernel<<<BTc*Hc, 256, SMEM_ATTN>>>();
    proj_o_kernel<<<Mc/128, 256, SMEM_PROJ>>>(Wo, bo, out);
}

// round 16
// speedup vs baseline: 1.5352x; 1.3765x over previous
#include <cuda_runtime.h>
#include <cuda_bf16.h>
#include <cuda_fp16.h>
#include <cstdint>

#define BTc 16
#define Nc 1024
#define Dc 128
#define Hc 8
#define HDc 16
#define Mc (BTc*Nc)

// ---- gmem scratch (no allocs allowed) ----
__device__ __half g_q16[(size_t)BTc*Hc*Nc*HDc];   // [slab][n][hd]
__device__ __half g_k16[(size_t)BTc*Hc*Nc*HDc];
__device__ __half g_vt16[(size_t)BTc*Hc*HDc*Nc];  // [slab][hd][n]
__device__ __half g_adjh[(size_t)BTc*Nc*Nc];      // fp16 adj (32MB)
__device__ float g_ctx[(size_t)Mc*Dc];

__device__ __forceinline__ float fast_ex2(float x){ float r; asm("ex2.approx.f32 %0,%1;":"=f"(r):"f"(x)); return r; }
__device__ __forceinline__ uint32_t smem_u32(const void* p){ uint32_t a; asm("{ .reg .u64 t; cvta.to.shared.u64 t, %1; cvt.u32.u64 %0, t; }":"=r"(a):"l"(p)); return a; }
__device__ __forceinline__ uint32_t packbf(float x, float y){
    __nv_bfloat162 t = __floats2bfloat162_rn(x, y);
    return *reinterpret_cast<uint32_t*>(&t);
}
__device__ __forceinline__ uint32_t packh2(float x, float y){
    __half2 t = __floats2half2_rn(x, y);              // .x = low half
    return *reinterpret_cast<uint32_t*>(&t);
}
// bf16 mma (projections)
__device__ __forceinline__ void mma16816(float* d, uint32_t a0,uint32_t a1,uint32_t a2,uint32_t a3,
                                         uint32_t b0,uint32_t b1){
    asm volatile("mma.sync.aligned.m16n8k16.row.col.f32.bf16.bf16.f32 "
        "{%0,%1,%2,%3},{%4,%5,%6,%7},{%8,%9},{%0,%1,%2,%3};"
        : "+f"(d[0]),"+f"(d[1]),"+f"(d[2]),"+f"(d[3])
        : "r"(a0),"r"(a1),"r"(a2),"r"(a3),"r"(b0),"r"(b1));
}
// fp16 mma (attention)
__device__ __forceinline__ void mma16816h(float* d, uint32_t a0,uint32_t a1,uint32_t a2,uint32_t a3,
                                          uint32_t b0,uint32_t b1){
    asm volatile("mma.sync.aligned.m16n8k16.row.col.f32.f16.f16.f32 "
        "{%0,%1,%2,%3},{%4,%5,%6,%7},{%8,%9},{%0,%1,%2,%3};"
        : "+f"(d[0]),"+f"(d[1]),"+f"(d[2]),"+f"(d[3])
        : "r"(a0),"r"(a1),"r"(a2),"r"(a3),"r"(b0),"r"(b1));
}
#define CP16(dst,src) asm volatile("cp.async.ca.shared.global [%0], [%1], 16;"::"r"(dst),"l"(src):"memory")
#define CP_COMMIT()   asm volatile("cp.async.commit_group;":::"memory")
#define CP_WAIT0()    asm volatile("cp.async.wait_group 0;":::"memory")

// attention smem layout (bytes); Q/K rows 24 halfs (48B), V rows 136 halfs (272B), adj rows 136 halfs
#define A_Q 0
#define A_K 12288
#define A_V 24576
#define A_ADJ 33280
#define ADJ_BUF 34816
#define SMEM_ATTN (A_ADJ + 2*ADJ_BUF)   // 102912

// projection smem (bf16x3 GEMM); tiles stride 136 bf16
#define SPITCH 136
#define P_XH 0
#define P_XL 34816
#define P_WH 69632
#define P_WL 104448
#define P_BIAS 139264
#define SMEM_PROJ 139776

// ============================================================
// adj f32 -> fp16 conversion (standalone, bandwidth-saturating grid)
// ============================================================
__global__ void __launch_bounds__(256) adj_conv_kernel(const float* __restrict__ adj)
{
    const float4* src = (const float4*)adj;
    uint2* dst = (uint2*)g_adjh;
    size_t base = (size_t)blockIdx.x * 4096;
    #pragma unroll 4
    for (int i = 0; i < 16; ++i) {
        size_t idx = base + (size_t)i*256 + threadIdx.x;
        float4 v = src[idx];
        __half2 a = __floats2half2_rn(v.x, v.y);
        __half2 b = __floats2half2_rn(v.z, v.w);
        dst[idx] = make_uint2(*(uint32_t*)&a, *(uint32_t*)&b);
    }
}

// ============================================================
// Shared bf16x3 GEMM tile: C[128,128] = X @ W^T  (unchanged, accurate)
// ============================================================
__device__ __forceinline__ void proj_mma_tile(const float* __restrict__ Xg,
                                              const float* __restrict__ Wg,
                                              const float* __restrict__ bias,
                                              char* smc, int m0, float acc[16][4])
{
    int tid = threadIdx.x;
    __nv_bfloat16* Xh = (__nv_bfloat16*)(smc + P_XH);
    __nv_bfloat16* Xl = (__nv_bfloat16*)(smc + P_XL);
    __nv_bfloat16* Wh = (__nv_bfloat16*)(smc + P_WH);
    __nv_bfloat16* Wl = (__nv_bfloat16*)(smc + P_WL);
    float* bias_s = (float*)(smc + P_BIAS);
    if (tid < 128) bias_s[tid] = bias[tid];

    #pragma unroll
    for (int it = 0; it < 16; ++it) {
        int idx = it*256 + tid; int m = idx >> 5, k4 = (idx & 31)*4;
        float4 v = *(const float4*)(Xg + (size_t)(m0+m)*128 + k4);
        uint32_t H0 = packbf(v.x, v.y), H1 = packbf(v.z, v.w);
        float r0 = v.x - __uint_as_float(H0 << 16);
        float r1 = v.y - __uint_as_float(H0 & 0xffff0000u);
        float r2 = v.z - __uint_as_float(H1 << 16);
        float r3 = v.w - __uint_as_float(H1 & 0xffff0000u);
        *(uint2*)(Xh + m*SPITCH + k4) = make_uint2(H0, H1);
        *(uint2*)(Xl + m*SPITCH + k4) = make_uint2(packbf(r0, r1), packbf(r2, r3));
        float4 w = *(const float4*)(Wg + (size_t)m*128 + k4);
        uint32_t G0 = packbf(w.x, w.y), G1 = packbf(w.z, w.w);
        float s0 = w.x - __uint_as_float(G0 << 16);
        float s1 = w.y - __uint_as_float(G0 & 0xffff0000u);
        float s2 = w.z - __uint_as_float(G1 << 16);
        float s3 = w.w - __uint_as_float(G1 & 0xffff0000u);
        *(uint2*)(Wh + m*SPITCH + k4) = make_uint2(G0, G1);
        *(uint2*)(Wl + m*SPITCH + k4) = make_uint2(packbf(s0, s1), packbf(s2, s3));
    }
    __syncthreads();

    int w = tid >> 5, l = tid & 31;
    int g = l >> 2, c2 = (l & 3)*2;
    int m0w = w*16;
    #pragma unroll
    for (int j = 0; j < 16; ++j) { acc[j][0]=0.f; acc[j][1]=0.f; acc[j][2]=0.f; acc[j][3]=0.f; }

    #pragma unroll
    for (int ks = 0; ks < 8; ++ks) {
        int kb = ks*16;
        uint32_t ah0 = *(const uint32_t*)(Xh + (m0w+g)*SPITCH + kb + c2);
        uint32_t ah1 = *(const uint32_t*)(Xh + (m0w+g+8)*SPITCH + kb + c2);
        uint32_t ah2 = *(const uint32_t*)(Xh + (m0w+g)*SPITCH + kb + c2 + 8);
        uint32_t ah3 = *(const uint32_t*)(Xh + (m0w+g+8)*SPITCH + kb + c2 + 8);
        uint32_t al0 = *(const uint32_t*)(Xl + (m0w+g)*SPITCH + kb + c2);
        uint32_t al1 = *(const uint32_t*)(Xl + (m0w+g+8)*SPITCH + kb + c2);
        uint32_t al2 = *(const uint32_t*)(Xl + (m0w+g)*SPITCH + kb + c2 + 8);
        uint32_t al3 = *(const uint32_t*)(Xl + (m0w+g+8)*SPITCH + kb + c2 + 8);
        #pragma unroll
        for (int j = 0; j < 16; ++j) {
            int n0 = 8*j;
            uint32_t bh0 = *(const uint32_t*)(Wh + (n0+g)*SPITCH + kb + c2);
            uint32_t bh1 = *(const uint32_t*)(Wh + (n0+g)*SPITCH + kb + c2 + 8);
            uint32_t bl0 = *(const uint32_t*)(Wl + (n0+g)*SPITCH + kb + c2);
            uint32_t bl1 = *(const uint32_t*)(Wl + (n0+g)*SPITCH + kb + c2 + 8);
            mma16816(acc[j], ah0,ah1,ah2,ah3, bh0,bh1);
            mma16816(acc[j], ah0,ah1,ah2,ah3, bl0,bl1);
            mma16816(acc[j], al0,al1,al2,al3, bh0,bh1);
        }
    }
    __syncthreads();
}

// ============================================================
// QKV projection (bf16x3 GEMM) -> single fp16 outputs, staged coalesced
// ============================================================
__global__ void __launch_bounds__(256) proj_qkv_kernel(
    const float* __restrict__ x,
    const float* __restrict__ Wq, const float* __restrict__ bq,
    const float* __restrict__ Wk, const float* __restrict__ bk,
    const float* __restrict__ Wv, const float* __restrict__ bv)
{
    extern __shared__ char smc[];
    int sel = blockIdx.y;
    const float* W    = (sel==0)?Wq:(sel==1)?Wk:Wv;
    const float* bias = (sel==0)?bq:(sel==1)?bk:bv;
    float scale = (sel==0)?(0.25f*1.4426950408889634f):1.0f;
    int m0 = blockIdx.x * 128;

    float acc[16][4];
    proj_mma_tile(x, W, bias, smc, m0, acc);

    float* bias_s = (float*)(smc + P_BIAS);
    __half* Sh = (__half*)smc;       // 16384 halfs = 32KB staging
    int tid = threadIdx.x, w = tid >> 5, l = tid & 31;
    int g = l >> 2, c2 = (l & 3)*2;
    int r0 = w*16 + g, r1 = r0 + 8;

    #pragma unroll
    for (int j = 0; j < 16; ++j) {
        int n0 = 8*j;
        #pragma unroll
        for (int e = 0; e < 4; ++e) {
            int col = n0 + c2 + (e & 1);
            int r = (e < 2) ? r0 : r1;
            float v = (acc[j][e] + bias_s[col]) * scale;
            int head = col >> 4, hd = col & 15;
            int off = (sel < 2) ? (head*2048 + r*16 + hd)
                                : (head*2048 + hd*128 + r);
            Sh[off] = __float2half_rn(v);
        }
    }
    __syncthreads();

    int bt = m0 / Nc, nbase = m0 % Nc;
    __half* G = (sel==0)?g_q16:(sel==1)?g_k16:g_vt16;
    const uint4* sh4 = (const uint4*)Sh;
    #pragma unroll
    for (int it = 0; it < 8; ++it) {
        int i4 = it*256 + tid;                 // 0..2047
        int head = i4 >> 8, rem = i4 & 255;    // 256 uint4 (4KB) per head
        if (sel < 2) {
            size_t gbase = (((size_t)(bt*Hc + head))*Nc + nbase)*HDc;
            ((uint4*)(G + gbase))[rem] = sh4[i4];
        } else {
            int hd = rem >> 4, n8 = rem & 15;
            size_t gbase = ((size_t)(bt*Hc + head))*HDc*Nc + (size_t)hd*Nc + nbase;
            ((uint4*)(G + gbase))[n8] = sh4[i4];
        }
    }
}

// ============================================================
// O projection (bf16x3, unchanged)
// ============================================================
__global__ void __launch_bounds__(256) proj_o_kernel(
    const float* __restrict__ Wo, const float* __restrict__ bo, float* __restrict__ out)
{
    extern __shared__ char smc[];
    int m0 = blockIdx.x * 128;
    float acc[16][4];
    proj_mma_tile(g_ctx, Wo, bo, smc, m0, acc);

    float* bias_s = (float*)(smc + P_BIAS);
    float* Sf = (float*)smc;   // [128][132]
    int tid = threadIdx.x, w = tid >> 5, l = tid & 31;
    int g = l >> 2, c2 = (l & 3)*2;
    int r0 = w*16 + g, r1 = r0 + 8;
    #pragma unroll
    for (int j = 0; j < 16; ++j) {
        int n0 = 8*j;
        Sf[r0*132 + n0 + c2]     = acc[j][0] + bias_s[n0 + c2];
        Sf[r0*132 + n0 + c2 + 1] = acc[j][1] + bias_s[n0 + c2 + 1];
        Sf[r1*132 + n0 + c2]     = acc[j][2] + bias_s[n0 + c2];
        Sf[r1*132 + n0 + c2 + 1] = acc[j][3] + bias_s[n0 + c2 + 1];
    }
    __syncthreads();
    #pragma unroll
    for (int it = 0; it < 16; ++it) {
        int i4 = it*256 + tid;
        int row = i4 >> 5, c4 = (i4 & 31)*4;
        *(float4*)(out + (size_t)(m0+row)*128 + c4) = *(const float4*)(Sf + row*132 + c4);
    }
}

// ============================================================
// fp16 single-term warp-MMA flash attention (R12 shape: 256 thr, 8 warps,
// warp = 16 q-rows x 128 cols).  32 mma/warp/iter (3x fewer than bf16x3);
// epilogue has no lo-split.  adj fp16, Q/K/V fp16.
// ============================================================
__device__ __forceinline__ void issue_loads(int it, int t, uint32_t sb,
    const __half* gq, const __half* gk, const __half* gv, const __half* adjh)
{
    int qt = it >> 3, ch = it & 7, b = it & 1;
    int row = t >> 1, hw = t & 1;
    CP16(sb + A_K + b*6144 + row*48 + hw*16, gk + (ch*128+row)*16 + hw*8);
    int vg = t >> 4, vp = t & 15;
    CP16(sb + A_V + b*4352 + vg*272 + vp*16, gv + vg*1024 + ch*128 + vp*8);
    #pragma unroll
    for (int i = 0; i < 8; ++i) {
        int e = i*256 + t, r2 = e >> 4, q8 = e & 15;   // 128 rows x 16 x 16B
        CP16(sb + A_ADJ + b*ADJ_BUF + r2*272 + q8*16,
             adjh + (size_t)(qt*128 + r2)*1024 + ch*128 + q8*8);
    }
    if (ch == 0) {
        int qb = qt & 1;
        CP16(sb + A_Q + qb*6144 + row*48 + hw*16, gq + (qt*128+row)*16 + hw*8);
    }
    CP_COMMIT();
}

__global__ void __launch_bounds__(256,1) attn_mma_kernel()
{
    extern __shared__ char smc[];
    uint32_t sb = smem_u32(smc);
    int t = threadIdx.x, w = t >> 5, l = t & 31;
    int g = l >> 2, c2 = (l & 3)*2;
    int bt = blockIdx.x >> 3, h = blockIdx.x & 7, slab = bt*Hc + h;
    int m0 = w*16;

    const __half* gq = g_q16 + (size_t)slab*Nc*HDc;
    const __half* gk = g_k16 + (size_t)slab*Nc*HDc;
    const __half* gv = g_vt16 + (size_t)slab*HDc*Nc;
    const __half* adjh = g_adjh + ((size_t)bt << 20);

    uint32_t q0=0,q1=0,q2=0,q3=0;
    float ctx0[4], ctx1[4], sum0 = 0.f, sum1 = 0.f;

    issue_loads(0, t, sb, gq, gk, gv, adjh);

    for (int it = 0; it < 64; ++it) {
        CP_WAIT0();
        __syncthreads();
        if (it < 63) issue_loads(it+1, t, sb, gq, gk, gv, adjh);

        int qt = it >> 3, ch = it & 7, b = it & 1;
        const __half* sK = (const __half*)(smc + A_K + b*6144);
        const __half* sV = (const __half*)(smc + A_V + b*4352);
        const __half* sAdj = (const __half*)(smc + A_ADJ + b*ADJ_BUF);

        if (ch == 0) {
            const __half* sQ = (const __half*)(smc + A_Q + (qt&1)*6144);
            q0 = *(const uint32_t*)(sQ + (m0+g)*24 + c2);
            q1 = *(const uint32_t*)(sQ + (m0+g+8)*24 + c2);
            q2 = *(const uint32_t*)(sQ + (m0+g)*24 + c2 + 8);
            q3 = *(const uint32_t*)(sQ + (m0+g+8)*24 + c2 + 8);
            ctx0[0]=ctx0[1]=ctx0[2]=ctx0[3]=0.f;
            ctx1[0]=ctx1[1]=ctx1[2]=ctx1[3]=0.f;
            sum0 = 0.f; sum1 = 0.f;
        }

        // ---- S = Q K^T (fp16 single) ----
        float sacc[16][4];
        #pragma unroll
        for (int j = 0; j < 16; ++j) { sacc[j][0]=0.f; sacc[j][1]=0.f; sacc[j][2]=0.f; sacc[j][3]=0.f; }
        #pragma unroll
        for (int j = 0; j < 16; ++j) {
            int n0 = 8*j;
            uint32_t b0 = *(const uint32_t*)(sK + (n0+g)*24 + c2);
            uint32_t b1 = *(const uint32_t*)(sK + (n0+g)*24 + c2 + 8);
            mma16816h(sacc[j], q0,q1,q2,q3, b0,b1);
        }

        // ---- epilogue: p = ex2(s)*adj, pack fp16 A-frags ----
        uint32_t pA[16], pB[16];
        #pragma unroll
        for (int j = 0; j < 16; ++j) {
            __half2 hA2 = *(const __half2*)(sAdj + (m0+g)*136 + 8*j + c2);
            __half2 hB2 = *(const __half2*)(sAdj + (m0+g+8)*136 + 8*j + c2);
            float2 aA = __half22float2(hA2);
            float2 aB = __half22float2(hB2);
            float p0 = fast_ex2(sacc[j][0]) * aA.x;
            float p1 = fast_ex2(sacc[j][1]) * aA.y;
            float p2 = fast_ex2(sacc[j][2]) * aB.x;
            float p3 = fast_ex2(sacc[j][3]) * aB.y;
            sum0 += p0 + p1; sum1 += p2 + p3;
            pA[j] = packh2(p0, p1);
            pB[j] = packh2(p2, p3);
        }

        // ---- ctx += P V (fp16 single) ----
        #pragma unroll
        for (int kk = 0; kk < 8; ++kk) {
            int k0 = 16*kk;
            uint32_t v0 = *(const uint32_t*)(sV + g*136 + k0 + c2);
            uint32_t v1 = *(const uint32_t*)(sV + g*136 + k0 + c2 + 8);
            uint32_t w0 = *(const uint32_t*)(sV + (g+8)*136 + k0 + c2);
            uint32_t w1 = *(const uint32_t*)(sV + (g+8)*136 + k0 + c2 + 8);
            uint32_t a0 = pA[2*kk], a1 = pB[2*kk], a2 = pA[2*kk+1], a3 = pB[2*kk+1];
            mma16816h(ctx0, a0,a1,a2,a3, v0,v1);
            mma16816h(ctx1, a0,a1,a2,a3, w0,w1);
        }

        if (ch == 7) {
            float s0 = sum0, s1 = sum1;
            s0 += __shfl_xor_sync(0xffffffffu, s0, 1);
            s0 += __shfl_xor_sync(0xffffffffu, s0, 2);
            s1 += __shfl_xor_sync(0xffffffffu, s1, 1);
            s1 += __shfl_xor_sync(0xffffffffu, s1, 2);
            float inv0 = 1.0f / (s0 + 1e-8f), inv1 = 1.0f / (s1 + 1e-8f);
            int qr = qt*128 + m0 + g;
            float* op  = g_ctx + ((size_t)(bt*Nc + qr))*Dc + h*HDc;
            float* op2 = op + 8*Dc;
            float2 o;
            o.x = ctx0[0]*inv0; o.y = ctx0[1]*inv0; *(float2*)(op + c2) = o;
            o.x = ctx1[0]*inv0; o.y = ctx1[1]*inv0; *(float2*)(op + 8 + c2) = o;
            o.x = ctx0[2]*inv1; o.y = ctx0[3]*inv1; *(float2*)(op2 + c2) = o;
            o.x = ctx1[2]*inv1; o.y = ctx1[3]*inv1; *(float2*)(op2 + 8 + c2) = o;
        }
    }
}

// ============================================================
extern "C" void kernel_launch(void* const* d_in, const int* in_sizes, int n_in,
                              void* d_out, int out_size)
{
    const float* x   = (const float*)d_in[0];
    const float* adj = (const float*)d_in[1];
    const float* Wq  = (const float*)d_in[2];
    const float* bq  = (const float*)d_in[3];
    const float* Wk  = (const float*)d_in[4];
    const float* bk  = (const float*)d_in[5];
    const float* Wv  = (const float*)d_in[6];
    const float* bv  = (const float*)d_in[7];
    const float* Wo  = (const float*)d_in[8];
    const float* bo  = (const float*)d_in[9];
    float* out = (float*)d_out;

    cudaFuncSetAttribute(proj_qkv_kernel, cudaFuncAttributeMaxDynamicSharedMemorySize, SMEM_PROJ);
    cudaFuncSetAttribute(proj_o_kernel,   cudaFuncAttributeMaxDynamicSharedMemorySize, SMEM_PROJ);
    cudaFuncSetAttribute(attn_mma_kernel, cudaFuncAttributeMaxDynamicSharedMemorySize, SMEM_ATTN);

    adj_conv_kernel<<<1024, 256>>>(adj);                       // 96MB stream, saturating grid
    dim3 gqkv(Mc/128, 3);
    proj_qkv_kernel<<<gqkv, 256, SMEM_PROJ>>>(x, Wq, bq, Wk, bk, Wv, bv);
    attn_mma_kernel<<<BTc*Hc, 256, SMEM_ATTN>>>();
    proj_o_kernel<<<Mc/128, 256, SMEM_PROJ>>>(Wo, bo, out);
}